// round 10
// baseline (speedup 1.0000x reference)
#include <cuda_runtime.h>
#include <cuda_bf16.h>
#include <cstdint>
#include <cstdio>

// Problem dims (PureCorrelation_80796924773031): B=4, S=4096, E=512
#define B_ 4
#define S_ 4096
#define E_ 512

// -------------------- scratch (device globals; no allocs) ------------------
__device__ float g_q  [(size_t)B_ * S_ * E_];
__device__ float g_k  [(size_t)B_ * S_ * E_];
__device__ float g_v  [(size_t)B_ * S_ * E_];
__device__ float g_W1T[E_ * E_];       // W1 transposed: W1T[e][f] = W1[f][e]
__device__ float g_W2T[E_ * E_];
__device__ float g_b1 [E_];
__device__ float g_b2 [E_];
__device__ float g_kproj [(size_t)B_ * S_ * E_];   // [b][k][f]
__device__ float g_vproj [(size_t)B_ * S_ * E_];   // [b][k][e]
__device__ float g_kprojT[(size_t)B_ * E_ * S_];   // [b][f][k]
__device__ float g_alpha [(size_t)B_ * S_ * (size_t)S_];   // 256 MB
__device__ int   g_flags[8];   // [0..6] bf16 flags, [7] mask mode

// ===========================================================================
// Diagnostics: print raw views of all 8 input buffers (hex + float + stats)
// ===========================================================================
__global__ void diag_inputs_kernel(const void* p0, const void* p1,
                                   const void* p2, const void* p3,
                                   const void* p4, const void* p5,
                                   const void* p6, const void* p7)
{
    const void* ps[8] = {p0, p1, p2, p3, p4, p5, p6, p7};
    for (int i = 0; i < 8; i++) {
        const unsigned int* w = (const unsigned int*)ps[i];
        float ma = 0.f; int z = 0, o = 0;
        for (int j = 0; j < 64; j++) {
            float f = __uint_as_float(w[j]);
            ma += fabsf(f) < 1e30f ? fabsf(f) : 0.f;
            if (w[j] == 0u) z++;
            if (w[j] == 1u) o++;
        }
        printf("DIAG in%d w0=%08x w1=%08x w2=%08x w3=%08x f0=%.4e ma=%.3e z=%d o=%d\n",
               i, w[0], w[1], w[2], w[3],
               (double)__uint_as_float(w[0]), (double)(ma / 64.f), z, o);
    }
}

__global__ void diag_stage_kernel()
{
    int nz = 0;
    for (int j = 0; j < 1024; j++) if (g_alpha[j] != 0.f) nz++;
    printf("DIAG kp0=%.4e kp1=%.4e vp0=%.4e a0=%.4e a1=%.4e a2=%.4e anz=%d/1024 fl=%d%d%d%d%d%d%d m=%d\n",
           (double)g_kproj[0], (double)g_kproj[1], (double)g_vproj[0],
           (double)g_alpha[0], (double)g_alpha[1], (double)g_alpha[2], nz,
           g_flags[0], g_flags[1], g_flags[2], g_flags[3], g_flags[4],
           g_flags[5], g_flags[6], g_flags[7]);
}

__global__ void diag_out_kernel(const void* out)
{
    const float* fo = (const float*)out;
    printf("DIAG out f32: %.4e %.4e %.4e %.4e\n",
           (double)fo[0], (double)fo[1], (double)fo[2], (double)fo[3]);
}

// ===========================================================================
// Dtype sniff: bf16 elements put a plausible exponent (or zero) in the LOW 16
// bits of ~every 32-bit word; f32 mantissa noise hits ~18%. 256 words decide.
// ===========================================================================
__global__ void detect_dtype_kernel(const unsigned int* __restrict__ src, int idx)
{
    __shared__ int cnt;
    if (threadIdx.x == 0) cnt = 0;
    __syncthreads();
    unsigned int w  = src[threadIdx.x];
    unsigned int lo = w & 0xFFFFu;
    unsigned int e  = (lo >> 7) & 0xFFu;
    int hit = (lo == 0u) || (e >= 96u && e <= 141u);
    atomicAdd(&cnt, hit);
    __syncthreads();
    if (threadIdx.x == 0) g_flags[idx] = (cnt >= 200) ? 1 : 0;
}

// Mask width: 1 = bf16 halves, 2 = u8 bytes, 0 = 32-bit words.
__global__ void detect_mask_kernel(const unsigned int* __restrict__ src)
{
    __shared__ int bf, u8;
    if (threadIdx.x == 0) { bf = 0; u8 = 0; }
    __syncthreads();
    int lbf = 0, lu8 = 0;
    for (int i = threadIdx.x; i < 2048; i += 256) {
        unsigned int w = src[i];
        if ((w & 0xFFFFu) == 0x3F80u) lbf = 1;
        if ((w & 0xFEFEFEFEu) == 0u && (w & 0xFFFFFF00u) != 0u) lu8 = 1;
    }
    if (lbf) atomicOr(&bf, 1);
    if (lu8) atomicOr(&u8, 1);
    __syncthreads();
    if (threadIdx.x == 0) g_flags[7] = bf ? 1 : (u8 ? 2 : 0);
}

// ===========================================================================
// Conversions to f32 scratch
// ===========================================================================
__global__ void cvt_kernel(const void* __restrict__ src, int n, int flag_idx,
                           int dst_sel)
{
    float* dst = (dst_sel == 0) ? g_q  : (dst_sel == 1) ? g_k  :
                 (dst_sel == 2) ? g_v  : (dst_sel == 4) ? g_b1 : g_b2;
    const int bf = g_flags[flag_idx];
    for (int i = blockIdx.x * blockDim.x + threadIdx.x; i < n;
         i += gridDim.x * blockDim.x) {
        dst[i] = bf ? __bfloat162float(((const __nv_bfloat16*)src)[i])
                    : ((const float*)src)[i];
    }
}

// Convert + transpose weight: WT[e*E + f] = W[f*E + e]
__global__ void cvt_w_kernel(const void* __restrict__ src, int flag_idx, int which)
{
    float* dst = which ? g_W2T : g_W1T;
    const int bf = g_flags[flag_idx];
    for (int i = blockIdx.x * blockDim.x + threadIdx.x; i < E_ * E_;
         i += gridDim.x * blockDim.x) {
        int f = i / E_, e = i % E_;
        float v = bf ? __bfloat162float(((const __nv_bfloat16*)src)[i])
                     : ((const float*)src)[i];
        dst[e * E_ + f] = v;
    }
}

// ===========================================================================
// Naive, trivially-verifiable compute kernels
// ===========================================================================

// kproj[m][f] = sum_e key[m][e] * W1[f][e] + b1[f]   (via W1T[e][f])
__global__ void __launch_bounds__(256)
proj_naive(int which)
{
    const float* __restrict__ A  = which ? g_v   : g_k;
    const float* __restrict__ WT = which ? g_W2T : g_W1T;
    const float* __restrict__ bs = which ? g_b2  : g_b1;
    float* __restrict__ C        = which ? g_vproj : g_kproj;

    const int m = blockIdx.y;                       // 0..B*S-1
    const int f = blockIdx.x * 256 + threadIdx.x;   // 0..E-1
    float acc = bs[f];
    const float* arow = A + (size_t)m * E_;
    for (int e = 0; e < E_; e++)
        acc += arow[e] * WT[e * E_ + f];            // arow[e] broadcast; WT coalesced
    C[(size_t)m * E_ + f] = acc;
}

// kprojT[b][f][k] = kproj[b][k][f]
__global__ void transpose_kp_kernel()
{
    const size_t n = (size_t)B_ * S_ * E_;
    for (size_t i = blockIdx.x * (size_t)blockDim.x + threadIdx.x; i < n;
         i += (size_t)gridDim.x * blockDim.x) {
        size_t b = i / ((size_t)S_ * E_);
        size_t r = i % ((size_t)S_ * E_);
        size_t k = r / E_, e = r % E_;
        g_kprojT[b * E_ * S_ + e * S_ + k] = g_kproj[i];
    }
}

// alpha[b][q][k] = (mask||k==0) ? max(sum_e q[b,q,e]*kproj[b,k,e], 0) : 0
__global__ void __launch_bounds__(256)
scores_naive(const void* __restrict__ mask_raw)
{
    const int b = blockIdx.z;
    const int q = blockIdx.y;
    const int k = blockIdx.x * 256 + threadIdx.x;

    const float* __restrict__ qrow = g_q + ((size_t)b * S_ + q) * E_;
    const float* __restrict__ KT   = g_kprojT + (size_t)b * E_ * S_;
    float acc = 0.f;
    for (int e = 0; e < E_; e++)
        acc += qrow[e] * KT[(size_t)e * S_ + k];    // qrow[e] broadcast; KT coalesced

    const size_t midx = (size_t)b * S_ * S_ + (size_t)q * S_ + k;
    const int mode = g_flags[7];
    bool mv;
    if (mode == 1)      mv = (((const unsigned short*)mask_raw)[midx] != 0);
    else if (mode == 2) mv = (((const unsigned char*) mask_raw)[midx] != 0);
    else                mv = (((const unsigned int*)  mask_raw)[midx] != 0u);
    bool keep = (k == 0) || mv;
    g_alpha[midx] = (keep && acc > 0.f) ? acc : 0.f;
}

// out[b][q][e] = sum_k alpha[b][q][k] * vproj[b][k][e]
__global__ void __launch_bounds__(256)
out_naive(void* __restrict__ Out)
{
    const int b = blockIdx.z;
    const int q = blockIdx.y;
    const int e = blockIdx.x * 256 + threadIdx.x;

    const float* __restrict__ arow = g_alpha + (size_t)b * S_ * S_ + (size_t)q * S_;
    const float* __restrict__ VP   = g_vproj + (size_t)b * S_ * E_;
    float acc = 0.f;
    for (int k = 0; k < S_; k++)
        acc += arow[k] * VP[(size_t)k * E_ + e];    // arow[k] broadcast; VP coalesced

    const size_t oidx = ((size_t)b * S_ + q) * E_ + e;
    if (g_flags[0])
        ((__nv_bfloat16*)Out)[oidx] = __float2bfloat16(acc);
    else
        ((float*)Out)[oidx] = acc;
}

// ===========================================================================
// Launch
// ===========================================================================
extern "C" void kernel_launch(void* const* d_in, const int* in_sizes, int n_in,
                              void* d_out, int out_size)
{
    // ---- host-side diagnostics (run only on correctness/capture calls) ----
    printf("HDIAG n_in=%d out_size=%d\n", n_in, out_size);
    for (int i = 0; i < n_in && i < 12; i++)
        printf("HDIAG in[%d] size=%d align=%d\n", i, in_sizes[i],
               (int)((uintptr_t)d_in[i] & 0xFFu));
    fflush(stdout);

    const int SZ_QKV = B_ * S_ * E_;          // 8,388,608
    const int SZ_W   = E_ * E_;               // 262,144
    const int SZ_MSK = B_ * S_ * S_;          // 67,108,864

    const void* big[3] = {0, 0, 0};  int nbig = 0;
    const void* w[2]   = {0, 0};     int nw = 0;
    const void* bias[2]= {0, 0};     int nb = 0;
    const void* mask   = 0;

    for (int i = 0; i < n_in; i++) {
        int s = in_sizes[i];
        if (s == SZ_QKV && nbig < 3)   big[nbig++] = d_in[i];
        else if (s == SZ_W && nw < 2)  w[nw++]     = d_in[i];
        else if (s == E_ && nb < 2)    bias[nb++]  = d_in[i];
        else if (s == SZ_MSK)          mask        = d_in[i];
    }
    printf("HDIAG classified nbig=%d nw=%d nb=%d mask=%d\n",
           nbig, nw, nb, mask != 0);
    fflush(stdout);

    // Insertion-order appearance: query, key, value / W1, W2 / b1, b2
    const void* query = big[0];
    const void* key   = big[1];
    const void* value = big[2];
    const void* W1 = w[0];
    const void* W2 = w[1];
    const void* b1 = bias[0];
    const void* b2 = bias[1];

    // device-side raw-input dump
    diag_inputs_kernel<<<1, 1>>>(d_in[0], d_in[1], d_in[2], d_in[3],
                                 d_in[4], d_in[5], d_in[6], d_in[7]);

    // 0) dtype / mask-width detection
    detect_dtype_kernel<<<1, 256>>>((const unsigned int*)query, 0);
    detect_dtype_kernel<<<1, 256>>>((const unsigned int*)key,   1);
    detect_dtype_kernel<<<1, 256>>>((const unsigned int*)value, 2);
    detect_dtype_kernel<<<1, 256>>>((const unsigned int*)W1,    3);
    detect_dtype_kernel<<<1, 256>>>((const unsigned int*)b1,    4);
    detect_dtype_kernel<<<1, 256>>>((const unsigned int*)W2,    5);
    detect_dtype_kernel<<<1, 256>>>((const unsigned int*)b2,    6);
    detect_mask_kernel<<<1, 256>>>((const unsigned int*)mask);

    // 1) convert to f32 scratch (+ weight transpose)
    cvt_kernel<<<4096, 256>>>(query, SZ_QKV, 0, 0);
    cvt_kernel<<<4096, 256>>>(key,   SZ_QKV, 1, 1);
    cvt_kernel<<<4096, 256>>>(value, SZ_QKV, 2, 2);
    cvt_w_kernel<<<512, 256>>>(W1, 3, 0);
    cvt_kernel<<<2,   256>>>(b1, E_, 4, 4);
    cvt_w_kernel<<<512, 256>>>(W2, 5, 1);
    cvt_kernel<<<2,   256>>>(b2, E_, 6, 5);

    // 2) projections (naive)
    {
        dim3 g(E_ / 256, B_ * S_);            // (2, 16384)
        proj_naive<<<g, 256>>>(0);
        proj_naive<<<g, 256>>>(1);
    }

    // 3) transpose kproj for coalesced scores
    transpose_kp_kernel<<<8192, 256>>>();

    // 4) scores + mask + relu (naive)
    {
        dim3 g(S_ / 256, S_, B_);             // (16, 4096, 4)
        scores_naive<<<g, 256>>>(mask);
    }
    diag_stage_kernel<<<1, 1>>>();

    // 5) out = alpha @ vproj (naive)
    {
        dim3 g(E_ / 256, S_, B_);             // (2, 4096, 4)
        out_naive<<<g, 256>>>(d_out);
    }
    diag_out_kernel<<<1, 1>>>(d_out);
}

// round 11
// speedup vs baseline: 3.5598x; 3.5598x over previous
#include <cuda_runtime.h>
#include <cuda_bf16.h>
#include <cstdint>

// Problem dims (PureCorrelation_80796924773031): B=4, S=4096, E=512
#define B_ 4
#define S_ 4096
#define E_ 512

#define QT  16     // row-tile per block (q rows / key rows)
#define PAD 20     // padded smem row stride in floats (80B, 16B-aligned)

// -------------------- scratch (device globals; no allocs) ------------------
__device__ float g_q  [(size_t)B_ * S_ * E_];
__device__ float g_k  [(size_t)B_ * S_ * E_];
__device__ float g_v  [(size_t)B_ * S_ * E_];
__device__ float g_W1T[E_ * E_];       // W1T[e][f] = W1[f][e]
__device__ float g_W2T[E_ * E_];
__device__ float g_b1 [E_];
__device__ float g_b2 [E_];
__device__ float g_kproj [(size_t)B_ * S_ * E_];   // [b][k][f]
__device__ float g_vproj [(size_t)B_ * S_ * E_];   // [b][k][e]
__device__ float g_kprojT[(size_t)B_ * E_ * S_];   // [b][f][k]
__device__ float g_alpha [(size_t)B_ * S_ * (size_t)S_];   // 256 MB
__device__ int   g_flags[8];   // [0..6] bf16 flags, [7] mask mode

// ===========================================================================
// Detection (unchanged from passing R10)
// ===========================================================================
__global__ void detect_dtype_kernel(const unsigned int* __restrict__ src, int idx)
{
    __shared__ int cnt;
    if (threadIdx.x == 0) cnt = 0;
    __syncthreads();
    unsigned int w  = src[threadIdx.x];
    unsigned int lo = w & 0xFFFFu;
    unsigned int e  = (lo >> 7) & 0xFFu;
    int hit = (lo == 0u) || (e >= 96u && e <= 141u);
    atomicAdd(&cnt, hit);
    __syncthreads();
    if (threadIdx.x == 0) g_flags[idx] = (cnt >= 200) ? 1 : 0;
}

__global__ void detect_mask_kernel(const unsigned int* __restrict__ src)
{
    __shared__ int bf, u8;
    if (threadIdx.x == 0) { bf = 0; u8 = 0; }
    __syncthreads();
    int lbf = 0, lu8 = 0;
    for (int i = threadIdx.x; i < 2048; i += 256) {
        unsigned int w = src[i];
        if ((w & 0xFFFFu) == 0x3F80u) lbf = 1;
        if ((w & 0xFEFEFEFEu) == 0u && (w & 0xFFFFFF00u) != 0u) lu8 = 1;
    }
    if (lbf) atomicOr(&bf, 1);
    if (lu8) atomicOr(&u8, 1);
    __syncthreads();
    if (threadIdx.x == 0) g_flags[7] = bf ? 1 : (u8 ? 2 : 0);
}

// ===========================================================================
// Conversions to f32 scratch (unchanged from passing R10)
// ===========================================================================
__global__ void cvt_kernel(const void* __restrict__ src, int n, int flag_idx,
                           int dst_sel)
{
    float* dst = (dst_sel == 0) ? g_q  : (dst_sel == 1) ? g_k  :
                 (dst_sel == 2) ? g_v  : (dst_sel == 4) ? g_b1 : g_b2;
    const int bf = g_flags[flag_idx];
    for (int i = blockIdx.x * blockDim.x + threadIdx.x; i < n;
         i += gridDim.x * blockDim.x) {
        dst[i] = bf ? __bfloat162float(((const __nv_bfloat16*)src)[i])
                    : ((const float*)src)[i];
    }
}

__global__ void cvt_w_kernel(const void* __restrict__ src, int flag_idx, int which)
{
    float* dst = which ? g_W2T : g_W1T;
    const int bf = g_flags[flag_idx];
    for (int i = blockIdx.x * blockDim.x + threadIdx.x; i < E_ * E_;
         i += gridDim.x * blockDim.x) {
        int f = i / E_, e = i % E_;
        float v = bf ? __bfloat162float(((const __nv_bfloat16*)src)[i])
                     : ((const float*)src)[i];
        dst[e * E_ + f] = v;
    }
}

// kprojT[b][f][k] = kproj[b][k][f]  (unchanged from passing R10)
__global__ void transpose_kp_kernel()
{
    const size_t n = (size_t)B_ * S_ * E_;
    for (size_t i = blockIdx.x * (size_t)blockDim.x + threadIdx.x; i < n;
         i += (size_t)gridDim.x * blockDim.x) {
        size_t b = i / ((size_t)S_ * E_);
        size_t r = i % ((size_t)S_ * E_);
        size_t k = r / E_, e = r % E_;
        g_kprojT[b * E_ * S_ + e * S_ + k] = g_kproj[i];
    }
}

// ===========================================================================
// Tiled compute: minimal-delta extension of the PASSING naive kernels.
// Pattern: block = (16-row tile, 256 output columns). Tile rows live in smem,
// transposed with padded stride. Inner loop: 1 coalesced LDG + 4 broadcast
// float4 LDS + 16 FFMA.
// ===========================================================================

// kproj[m][f] = sum_e key[m][e] * W1T[e][f] + b1[f]
// grid: (E_/256, (B_*S_)/QT), block 256
__global__ void __launch_bounds__(256)
proj_tiled(int which)
{
    __shared__ float rT[E_][PAD];           // rT[e][qi] = A[m0+qi][e]  (40 KB)

    const float* __restrict__ A  = which ? g_v   : g_k;
    const float* __restrict__ WT = which ? g_W2T : g_W1T;
    const float* __restrict__ bs = which ? g_b2  : g_b1;
    float* __restrict__ C        = which ? g_vproj : g_kproj;

    const int m0 = blockIdx.y * QT;
    const int f  = blockIdx.x * 256 + threadIdx.x;
    const int t  = threadIdx.x;

#pragma unroll
    for (int it = 0; it < (QT * E_) / 256; it++) {      // 32 iters
        int idx = it * 256 + t;
        int e   = idx & (E_ - 1);
        int qi  = idx >> 9;                              // E_ = 512 = 2^9
        rT[e][qi] = A[(size_t)(m0 + qi) * E_ + e];       // coalesced in e
    }
    __syncthreads();

    float acc[QT];
#pragma unroll
    for (int i = 0; i < QT; i++) acc[i] = 0.f;

#pragma unroll 4
    for (int e = 0; e < E_; e++) {
        float wv = WT[(size_t)e * E_ + f];               // coalesced, L2-hot
        const float4* row = (const float4*)&rT[e][0];    // 16B-aligned (80B rows)
        float4 a0 = row[0], a1 = row[1], a2 = row[2], a3 = row[3];
        acc[0]  += wv * a0.x;  acc[1]  += wv * a0.y;
        acc[2]  += wv * a0.z;  acc[3]  += wv * a0.w;
        acc[4]  += wv * a1.x;  acc[5]  += wv * a1.y;
        acc[6]  += wv * a1.z;  acc[7]  += wv * a1.w;
        acc[8]  += wv * a2.x;  acc[9]  += wv * a2.y;
        acc[10] += wv * a2.z;  acc[11] += wv * a2.w;
        acc[12] += wv * a3.x;  acc[13] += wv * a3.y;
        acc[14] += wv * a3.z;  acc[15] += wv * a3.w;
    }

    const float bias = bs[f];
#pragma unroll
    for (int i = 0; i < QT; i++)
        C[(size_t)(m0 + i) * E_ + f] = acc[i] + bias;
}

// alpha[b][q][k] = (mask||k==0) ? max(sum_e q[b,q,e]*kprojT[b,e,k], 0) : 0
// grid: (S_/256, S_/QT, B_), block 256
__global__ void __launch_bounds__(256)
scores_tiled(const void* __restrict__ mask_raw)
{
    __shared__ float qT[E_][PAD];           // qT[e][qi] = Q[q0+qi][e]  (40 KB)

    const int b  = blockIdx.z;
    const int q0 = blockIdx.y * QT;
    const int k  = blockIdx.x * 256 + threadIdx.x;
    const int t  = threadIdx.x;

    const float* __restrict__ Q  = g_q      + (size_t)b * S_ * E_;
    const float* __restrict__ KT = g_kprojT + (size_t)b * E_ * S_;

#pragma unroll
    for (int it = 0; it < (QT * E_) / 256; it++) {
        int idx = it * 256 + t;
        int e   = idx & (E_ - 1);
        int qi  = idx >> 9;
        qT[e][qi] = Q[(size_t)(q0 + qi) * E_ + e];
    }
    __syncthreads();

    float acc[QT];
#pragma unroll
    for (int i = 0; i < QT; i++) acc[i] = 0.f;

    const float* __restrict__ kcol = KT + k;
#pragma unroll 4
    for (int e = 0; e < E_; e++) {
        float kv = kcol[(size_t)e * S_];                 // coalesced, L2-hot
        const float4* row = (const float4*)&qT[e][0];
        float4 a0 = row[0], a1 = row[1], a2 = row[2], a3 = row[3];
        acc[0]  += kv * a0.x;  acc[1]  += kv * a0.y;
        acc[2]  += kv * a0.z;  acc[3]  += kv * a0.w;
        acc[4]  += kv * a1.x;  acc[5]  += kv * a1.y;
        acc[6]  += kv * a1.z;  acc[7]  += kv * a1.w;
        acc[8]  += kv * a2.x;  acc[9]  += kv * a2.y;
        acc[10] += kv * a2.z;  acc[11] += kv * a2.w;
        acc[12] += kv * a3.x;  acc[13] += kv * a3.y;
        acc[14] += kv * a3.z;  acc[15] += kv * a3.w;
    }

    const int mode = g_flags[7];
    const size_t base = (size_t)b * S_ * (size_t)S_;
#pragma unroll
    for (int i = 0; i < QT; i++) {
        size_t midx = base + (size_t)(q0 + i) * S_ + k;
        bool mv;
        if (mode == 1)      mv = (((const unsigned short*)mask_raw)[midx] != 0);
        else if (mode == 2) mv = (((const unsigned char*) mask_raw)[midx] != 0);
        else                mv = (((const unsigned int*)  mask_raw)[midx] != 0u);
        bool keep = (k == 0) || mv;
        float s = acc[i];
        g_alpha[midx] = (keep && s > 0.f) ? s : 0.f;
    }
}

// out[b][q][e] = sum_k alpha[b][q][k] * vproj[b][k][e]
// grid: (E_/256, S_/QT, B_), block 256. K tiled by 256 through smem.
#define KTILE 256
__global__ void __launch_bounds__(256)
out_tiled(void* __restrict__ Out)
{
    __shared__ float aT[KTILE][PAD];        // aT[kk][qi]  (20 KB)

    const int b  = blockIdx.z;
    const int q0 = blockIdx.y * QT;
    const int e  = blockIdx.x * 256 + threadIdx.x;
    const int t  = threadIdx.x;

    const float* __restrict__ AL = g_alpha + (size_t)b * S_ * (size_t)S_;
    const float* __restrict__ VP = g_vproj + (size_t)b * S_ * E_;

    float acc[QT];
#pragma unroll
    for (int i = 0; i < QT; i++) acc[i] = 0.f;

    for (int k0 = 0; k0 < S_; k0 += KTILE) {
        __syncthreads();                                 // protect prev tile
#pragma unroll
        for (int it = 0; it < (QT * KTILE) / 256; it++) {  // 16 iters
            int idx = it * 256 + t;
            int kk  = idx & (KTILE - 1);
            int qi  = idx >> 8;                          // KTILE = 256 = 2^8
            aT[kk][qi] = AL[(size_t)(q0 + qi) * S_ + k0 + kk];  // coalesced
        }
        __syncthreads();

#pragma unroll 4
        for (int kk = 0; kk < KTILE; kk++) {
            float vv = VP[(size_t)(k0 + kk) * E_ + e];   // coalesced, L2-hot
            const float4* row = (const float4*)&aT[kk][0];
            float4 a0 = row[0], a1 = row[1], a2 = row[2], a3 = row[3];
            acc[0]  += vv * a0.x;  acc[1]  += vv * a0.y;
            acc[2]  += vv * a0.z;  acc[3]  += vv * a0.w;
            acc[4]  += vv * a1.x;  acc[5]  += vv * a1.y;
            acc[6]  += vv * a1.z;  acc[7]  += vv * a1.w;
            acc[8]  += vv * a2.x;  acc[9]  += vv * a2.y;
            acc[10] += vv * a2.z;  acc[11] += vv * a2.w;
            acc[12] += vv * a3.x;  acc[13] += vv * a3.y;
            acc[14] += vv * a3.z;  acc[15] += vv * a3.w;
        }
    }

    if (g_flags[0]) {
        __nv_bfloat16* O = (__nv_bfloat16*)Out;
#pragma unroll
        for (int i = 0; i < QT; i++)
            O[((size_t)b * S_ + q0 + i) * E_ + e] = __float2bfloat16(acc[i]);
    } else {
        float* O = (float*)Out;
#pragma unroll
        for (int i = 0; i < QT; i++)
            O[((size_t)b * S_ + q0 + i) * E_ + e] = acc[i];
    }
}

// ===========================================================================
// Launch — identical dispatch to the PASSING R10
// ===========================================================================
extern "C" void kernel_launch(void* const* d_in, const int* in_sizes, int n_in,
                              void* d_out, int out_size)
{
    const int SZ_QKV = B_ * S_ * E_;          // 8,388,608
    const int SZ_W   = E_ * E_;               // 262,144
    const int SZ_MSK = B_ * S_ * S_;          // 67,108,864

    const void* big[3] = {0, 0, 0};  int nbig = 0;
    const void* w[2]   = {0, 0};     int nw = 0;
    const void* bias[2]= {0, 0};     int nb = 0;
    const void* mask   = 0;

    for (int i = 0; i < n_in; i++) {
        int s = in_sizes[i];
        if (s == SZ_QKV && nbig < 3)   big[nbig++] = d_in[i];
        else if (s == SZ_W && nw < 2)  w[nw++]     = d_in[i];
        else if (s == E_ && nb < 2)    bias[nb++]  = d_in[i];
        else if (s == SZ_MSK)          mask        = d_in[i];
    }

    const void* query = big[0];
    const void* key   = big[1];
    const void* value = big[2];
    const void* W1 = w[0];
    const void* W2 = w[1];
    const void* b1 = bias[0];
    const void* b2 = bias[1];

    // 0) dtype / mask-width detection
    detect_dtype_kernel<<<1, 256>>>((const unsigned int*)query, 0);
    detect_dtype_kernel<<<1, 256>>>((const unsigned int*)key,   1);
    detect_dtype_kernel<<<1, 256>>>((const unsigned int*)value, 2);
    detect_dtype_kernel<<<1, 256>>>((const unsigned int*)W1,    3);
    detect_dtype_kernel<<<1, 256>>>((const unsigned int*)b1,    4);
    detect_dtype_kernel<<<1, 256>>>((const unsigned int*)W2,    5);
    detect_dtype_kernel<<<1, 256>>>((const unsigned int*)b2,    6);
    detect_mask_kernel<<<1, 256>>>((const unsigned int*)mask);

    // 1) convert to f32 scratch (+ weight transpose)
    cvt_kernel<<<4096, 256>>>(query, SZ_QKV, 0, 0);
    cvt_kernel<<<4096, 256>>>(key,   SZ_QKV, 1, 1);
    cvt_kernel<<<4096, 256>>>(value, SZ_QKV, 2, 2);
    cvt_w_kernel<<<512, 256>>>(W1, 3, 0);
    cvt_kernel<<<2,   256>>>(b1, E_, 4, 4);
    cvt_w_kernel<<<512, 256>>>(W2, 5, 1);
    cvt_kernel<<<2,   256>>>(b2, E_, 6, 5);

    // 2) projections (tiled)
    {
        dim3 g(E_ / 256, (B_ * S_) / QT);     // (2, 1024)
        proj_tiled<<<g, 256>>>(0);
        proj_tiled<<<g, 256>>>(1);
    }

    // 3) transpose kproj for coalesced scores
    transpose_kp_kernel<<<8192, 256>>>();

    // 4) scores + mask + relu (tiled)
    {
        dim3 g(S_ / 256, S_ / QT, B_);        // (16, 256, 4)
        scores_tiled<<<g, 256>>>(mask);
    }

    // 5) out = alpha @ vproj (tiled)
    {
        dim3 g(E_ / 256, S_ / QT, B_);        // (2, 256, 4)
        out_tiled<<<g, 256>>>(d_out);
    }
}